// round 10
// baseline (speedup 1.0000x reference)
#include <cuda_runtime.h>
#include <math.h>
#include <stdint.h>

#define BB 128
#define TT 512
#define HH 1024
#define EE 128
#define NL 17
#define G3 3072
#define NCTA 128
#define KC 64          // h k-block
#define SHP 68         // h slab row stride (floats)
#define GXP 132        // sgx row stride

// ---------------- device scratch ----------------
__device__ float g_gxw[201326592];            // [B][T][3H]
__device__ uint32_t g_Ahi[67108864];          // we hi  [65536][1024]
__device__ uint32_t g_Alo[67108864];          // we lo
__device__ uint32_t g_Bhi[3145728];           // Wih[:,E:] hi [3072][1024]
__device__ uint32_t g_Blo[3145728];
__device__ float g_tbl[NL * G3];
__device__ float g_hbuf[2][BB * HH];
__device__ volatile unsigned g_pt[BB];        // packed (tag<<5)|pred
__device__ volatile unsigned g_flags[NCTA];

// ---------------- helpers ----------------
__device__ __forceinline__ float sigmoidf_(float x) { return 1.0f / (1.0f + expf(-x)); }

__device__ __forceinline__ float maskval(int prev, int nxt) {
    bool allowed;
    bool prev_open = (prev == 0) || (((prev - 1) & 3) >= 2);   // O, E-, S-
    if (prev_open) {
        allowed = (nxt == 0) || (((nxt - 1) & 3) == 0) || (((nxt - 1) & 3) == 3);
    } else {
        int ty = (prev - 1) >> 2;
        allowed = (nxt != 0) && (((nxt - 1) >> 2) == ty) &&
                  ((((nxt - 1) & 3) == 1) || (((nxt - 1) & 3) == 2));
    }
    return allowed ? 0.0f : -1e12f;
}

__device__ __forceinline__ void flatbar(int cta, int tid, unsigned e) {
    __syncthreads();
    __threadfence();
    if (tid == 0) g_flags[cta] = e;
    if (tid < NCTA) { while (g_flags[tid] < e) { } }
    __syncthreads();
    __threadfence();
}

__device__ __forceinline__ void split_tf32(float x, uint32_t& hi, uint32_t& lo) {
    asm("cvt.rna.tf32.f32 %0, %1;" : "=r"(hi) : "f"(x));
    float hif = __uint_as_float(hi);
    float lof = x - hif;
    asm("cvt.rna.tf32.f32 %0, %1;" : "=r"(lo) : "f"(lof));
}

__device__ __forceinline__ void mma_tf32(float* c, const uint32_t* a,
                                         uint32_t b0, uint32_t b1) {
    asm volatile(
        "mma.sync.aligned.m16n8k8.row.col.f32.tf32.tf32.f32 "
        "{%0,%1,%2,%3}, {%4,%5,%6,%7}, {%8,%9}, {%0,%1,%2,%3};"
        : "+f"(c[0]), "+f"(c[1]), "+f"(c[2]), "+f"(c[3])
        : "r"(a[0]), "r"(a[1]), "r"(a[2]), "r"(a[3]), "r"(b0), "r"(b1));
}

// ---------------- K0: reset persistent state ----------------
__global__ void reset_state() {
    int i = blockIdx.x * blockDim.x + threadIdx.x;
    if (i < BB * HH) g_hbuf[0][i] = 0.0f;
    if (i < NCTA) g_flags[i] = 0u;
    if (i < BB) g_pt[i] = 0u;
}

// ---------------- K1: label-embedding gate table ----------------
__global__ void build_table(const float* __restrict__ label_emb,
                            const float* __restrict__ W_ih,
                            const float* __restrict__ b_ih) {
    int j = blockIdx.x * blockDim.x + threadIdx.x;
    int l = blockIdx.y;
    if (j >= G3) return;
    const float* w = W_ih + (size_t)j * (EE + HH);
    const float* e = label_emb + l * EE;
    float s = b_ih[j];
#pragma unroll 8
    for (int k = 0; k < EE; k++) s += e[k] * w[k];
    g_tbl[l * G3 + j] = s;
}

// ---------------- pre-split kernels (gxw operands, rna) ----------------
__global__ void presplit_A(const float* __restrict__ we) {
    size_t i = (size_t)blockIdx.x * blockDim.x + threadIdx.x;
    size_t stride = (size_t)gridDim.x * blockDim.x;
    size_t n4 = (size_t)BB * TT * HH / 4;
    for (; i < n4; i += stride) {
        float4 v = ((const float4*)we)[i];
        uint4 hi, lo;
        split_tf32(v.x, hi.x, lo.x); split_tf32(v.y, hi.y, lo.y);
        split_tf32(v.z, hi.z, lo.z); split_tf32(v.w, hi.w, lo.w);
        ((uint4*)g_Ahi)[i] = hi;
        ((uint4*)g_Alo)[i] = lo;
    }
}

__global__ void presplit_B(const float* __restrict__ wih) {
    size_t i = (size_t)blockIdx.x * blockDim.x + threadIdx.x;
    size_t stride = (size_t)gridDim.x * blockDim.x;
    size_t n4 = (size_t)G3 * HH / 4;
    for (; i < n4; i += stride) {
        size_t r = i >> 8;
        size_t c4 = (i & 255) * 4;
        float4 v = *(const float4*)&wih[r * (EE + HH) + EE + c4];
        uint4 hi, lo;
        split_tf32(v.x, hi.x, lo.x); split_tf32(v.y, hi.y, lo.y);
        split_tf32(v.z, hi.z, lo.z); split_tf32(v.w, hi.w, lo.w);
        *(uint4*)&g_Bhi[r * HH + c4] = hi;
        *(uint4*)&g_Blo[r * HH + c4] = lo;
    }
}

// ---------------- K2: big GEMM, 3xTF32 TC, pre-split operands ----------------
#define KB 32
#define APAD 36
__global__ __launch_bounds__(256) void gxw_gemm_tc(void) {
    extern __shared__ uint32_t su[];
    uint32_t* sAhi = su;
    uint32_t* sAlo = sAhi + 128 * APAD;
    uint32_t* sBhi = sAlo + 128 * APAD;
    uint32_t* sBlo = sBhi + 256 * APAD;

    const int tid = threadIdx.x;
    const int lane = tid & 31;
    const int warp = tid >> 5;
    const int wm = (warp >> 2) * 64;
    const int wn = (warp & 3) * 64;
    const int m0 = blockIdx.y * 128;
    const int n0 = blockIdx.x * 256;
    const int lr = lane >> 2;
    const int lc = lane & 3;

    float acc[4][8][4];
#pragma unroll
    for (int i = 0; i < 4; i++)
#pragma unroll
        for (int j = 0; j < 8; j++)
#pragma unroll
            for (int q = 0; q < 4; q++) acc[i][j][q] = 0.0f;

    for (int kb = 0; kb < HH; kb += KB) {
        __syncthreads();
#pragma unroll
        for (int jj = 0; jj < 4; jj++) {
            int idx = tid + jj * 256;
            int r = idx >> 3, c4 = (idx & 7) * 4;
            size_t src = (size_t)(m0 + r) * HH + kb + c4;
            *(uint4*)&sAhi[r * APAD + c4] = *(const uint4*)&g_Ahi[src];
            *(uint4*)&sAlo[r * APAD + c4] = *(const uint4*)&g_Alo[src];
        }
#pragma unroll
        for (int jj = 0; jj < 8; jj++) {
            int idx = tid + jj * 256;
            int r = idx >> 3, c4 = (idx & 7) * 4;
            size_t src = (size_t)(n0 + r) * HH + kb + c4;
            *(uint4*)&sBhi[r * APAD + c4] = *(const uint4*)&g_Bhi[src];
            *(uint4*)&sBlo[r * APAD + c4] = *(const uint4*)&g_Blo[src];
        }
        __syncthreads();

#pragma unroll
        for (int ks = 0; ks < KB; ks += 8) {
            uint32_t ah[4][4], al[4][4];
#pragma unroll
            for (int i = 0; i < 4; i++) {
                int row = wm + i * 16 + lr;
                int cc = ks + lc;
                ah[i][0] = sAhi[row * APAD + cc];
                ah[i][1] = sAhi[(row + 8) * APAD + cc];
                ah[i][2] = sAhi[row * APAD + cc + 4];
                ah[i][3] = sAhi[(row + 8) * APAD + cc + 4];
                al[i][0] = sAlo[row * APAD + cc];
                al[i][1] = sAlo[(row + 8) * APAD + cc];
                al[i][2] = sAlo[row * APAD + cc + 4];
                al[i][3] = sAlo[(row + 8) * APAD + cc + 4];
            }
#pragma unroll
            for (int j = 0; j < 8; j++) {
                int cn = wn + j * 8 + lr;
                int ck = ks + lc;
                uint32_t bh0 = sBhi[cn * APAD + ck];
                uint32_t bh1 = sBhi[cn * APAD + ck + 4];
                uint32_t bl0 = sBlo[cn * APAD + ck];
                uint32_t bl1 = sBlo[cn * APAD + ck + 4];
#pragma unroll
                for (int i = 0; i < 4; i++) {
                    mma_tf32(acc[i][j], ah[i], bh0, bh1);
                    mma_tf32(acc[i][j], ah[i], bl0, bl1);
                    mma_tf32(acc[i][j], al[i], bh0, bh1);
                }
            }
        }
    }

#pragma unroll
    for (int i = 0; i < 4; i++) {
#pragma unroll
        for (int j = 0; j < 8; j++) {
            int row = m0 + wm + i * 16 + lr;
            int cn = n0 + wn + j * 8 + lc * 2;
            *(float2*)&g_gxw[(size_t)row * G3 + cn] =
                make_float2(acc[i][j][0], acc[i][j][1]);
            *(float2*)&g_gxw[(size_t)(row + 8) * G3 + cn] =
                make_float2(acc[i][j][2], acc[i][j][3]);
        }
    }
}

// ---------------- K3: persistent recurrent (R9 arithmetic, SW-pipelined) ----
// 128 CTAs x 256 threads. CTA c owns h-cols [8c, 8c+8).
// Thread (g=tid>>5, mi=tid&31): 4 batches x 1 col x 3 gates, sequential-k FMA.
// Per-accumulator FMA expressions and k-order are IDENTICAL to R9 (bit-exact);
// only load scheduling changed: operand-level register double-buffer so the
// next kk's 7 float4 operands load while the current kk's FMAs issue.
__global__ __launch_bounds__(256) void recurrent(const float* __restrict__ Whh,
                                                 const float* __restrict__ bhh,
                                                 const float* __restrict__ Wout,
                                                 const float* __restrict__ bout,
                                                 float* __restrict__ out) {
    extern __shared__ float smem[];
    float* shw  = smem;                     // [24][1024]
    float* shh  = shw + 24 * 1024;          // [2][128][SHP]
    float* sgx  = shh + 2 * BB * SHP;       // [24][GXP]
    float* srow = sgx + 24 * GXP;           // [1024]
    __shared__ float slog[NL];

    const int tid = threadIdx.x;
    const int cta = blockIdx.x;
    const int g   = tid >> 5;
    const int mi  = tid & 31;
    const int base = cta * 8;
    const int col  = base + g;
    const int hold_kb = base & ~(KC - 1);
    const int hold_off = col - hold_kb;

    // one-time: resident W (24 gate rows x 1024)
    for (int f4 = tid; f4 < 24 * 256; f4 += 256) {
        int m = f4 >> 8;
        int q = f4 & 255;
        int wrow = (m >> 3) * HH + base + (m & 7);
        *(float4*)&shw[m * 1024 + q * 4] =
            *(const float4*)&Whh[(size_t)wrow * HH + q * 4];
    }
    const float bhr = bhh[col];
    const float bhz = bhh[HH + col];
    const float bhn = bhh[2 * HH + col];
    __syncthreads();

    const float* wrow_r = &shw[g * 1024];
    const float* wrow_z = &shw[(8 + g) * 1024];
    const float* wrow_n = &shw[(16 + g) * 1024];

    int cur = 0;
    for (int t = 0; t < TT; t++) {
        const float* __restrict__ hin = g_hbuf[cur];
        float* __restrict__ hout = g_hbuf[cur ^ 1];

        // ---- coalesced gx staging (R9 verbatim) ----
#pragma unroll
        for (int j = 0; j < 12; j++) {
            int f = tid + j * 256;
            int gate = f >> 10;
            int b = (f >> 3) & 127;
            int c = f & 7;
            sgx[(gate * 8 + c) * GXP + b] =
                g_gxw[((size_t)b * TT + t) * G3 + gate * HH + base + c];
        }

        // ---- prefetch + store h block 0 ----
        float4 pf[8];
#pragma unroll
        for (int j = 0; j < 8; j++) {
            int f = tid + j * 256;
            int r = f >> 4, kq = f & 15;
            pf[j] = *(const float4*)&hin[r * HH + kq * 4];
        }
#pragma unroll
        for (int j = 0; j < 8; j++) {
            int f = tid + j * 256;
            int r = f >> 4, kq = f & 15;
            *(float4*)&shh[r * SHP + kq * 4] = pf[j];
        }
        __syncthreads();

        float ar[4] = {0, 0, 0, 0}, az[4] = {0, 0, 0, 0}, an[4] = {0, 0, 0, 0};
        float hold[4];

        for (int kb = 0; kb < HH; kb += KC) {
            const int buf = (kb >> 6) & 1;
            float* hb = shh + buf * BB * SHP;

            // gmem prefetch of next slab into regs (overlaps compute)
            if (kb + KC < HH) {
#pragma unroll
                for (int j = 0; j < 8; j++) {
                    int f = tid + j * 256;
                    int r = f >> 4, kq = f & 15;
                    pf[j] = *(const float4*)&hin[r * HH + kb + KC + kq * 4];
                }
            }

            if (kb == hold_kb) {
#pragma unroll
                for (int i = 0; i < 4; i++)
                    hold[i] = hb[(mi + 32 * i) * SHP + hold_off];
            }

            // ---- operand-level software pipeline over kk ----
            float4 ch0 = *(float4*)&hb[mi * SHP];
            float4 ch1 = *(float4*)&hb[(mi + 32) * SHP];
            float4 ch2 = *(float4*)&hb[(mi + 64) * SHP];
            float4 ch3 = *(float4*)&hb[(mi + 96) * SHP];
            float4 cwr = *(const float4*)&wrow_r[kb];
            float4 cwz = *(const float4*)&wrow_z[kb];
            float4 cwn = *(const float4*)&wrow_n[kb];

#pragma unroll
            for (int kk = 0; kk < KC; kk += 4) {
                float4 nh0, nh1, nh2, nh3, nwr, nwz, nwn;
                if (kk + 4 < KC) {
                    nh0 = *(float4*)&hb[mi * SHP + kk + 4];
                    nh1 = *(float4*)&hb[(mi + 32) * SHP + kk + 4];
                    nh2 = *(float4*)&hb[(mi + 64) * SHP + kk + 4];
                    nh3 = *(float4*)&hb[(mi + 96) * SHP + kk + 4];
                    nwr = *(const float4*)&wrow_r[kb + kk + 4];
                    nwz = *(const float4*)&wrow_z[kb + kk + 4];
                    nwn = *(const float4*)&wrow_n[kb + kk + 4];
                }
                // FMA expressions identical to R9 (per-acc k-ascending order)
                ar[0] += ch0.x * cwr.x + ch0.y * cwr.y + ch0.z * cwr.z + ch0.w * cwr.w;
                az[0] += ch0.x * cwz.x + ch0.y * cwz.y + ch0.z * cwz.z + ch0.w * cwz.w;
                an[0] += ch0.x * cwn.x + ch0.y * cwn.y + ch0.z * cwn.z + ch0.w * cwn.w;
                ar[1] += ch1.x * cwr.x + ch1.y * cwr.y + ch1.z * cwr.z + ch1.w * cwr.w;
                az[1] += ch1.x * cwz.x + ch1.y * cwz.y + ch1.z * cwz.z + ch1.w * cwz.w;
                an[1] += ch1.x * cwn.x + ch1.y * cwn.y + ch1.z * cwn.z + ch1.w * cwn.w;
                ar[2] += ch2.x * cwr.x + ch2.y * cwr.y + ch2.z * cwr.z + ch2.w * cwr.w;
                az[2] += ch2.x * cwz.x + ch2.y * cwz.y + ch2.z * cwz.z + ch2.w * cwz.w;
                an[2] += ch2.x * cwn.x + ch2.y * cwn.y + ch2.z * cwn.z + ch2.w * cwn.w;
                ar[3] += ch3.x * cwr.x + ch3.y * cwr.y + ch3.z * cwr.z + ch3.w * cwr.w;
                az[3] += ch3.x * cwz.x + ch3.y * cwz.y + ch3.z * cwz.z + ch3.w * cwz.w;
                an[3] += ch3.x * cwn.x + ch3.y * cwn.y + ch3.z * cwn.z + ch3.w * cwn.w;

                if (kk + 4 < KC) {
                    ch0 = nh0; ch1 = nh1; ch2 = nh2; ch3 = nh3;
                    cwr = nwr; cwz = nwz; cwn = nwn;
                }
            }

            // store prefetched next slab
            if (kb + KC < HH) {
                float* nb = shh + (buf ^ 1) * BB * SHP;
#pragma unroll
                for (int j = 0; j < 8; j++) {
                    int f = tid + j * 256;
                    int r = f >> 4, kq = f & 15;
                    *(float4*)&nb[r * SHP + kq * 4] = pf[j];
                }
            }
            __syncthreads();
        }

        // ---- epilogue (R9 verbatim): spin for prev labels, GRU update ----
#pragma unroll
        for (int i = 0; i < 4; i++) {
            int b = mi + 32 * i;
            unsigned v = g_pt[b];
            while ((v >> 5) < (unsigned)t) v = g_pt[b];
            int pv = (int)(v & 31u);
            const float* tb = g_tbl + pv * G3;

            float xr = sgx[g * GXP + b]        + tb[col];
            float xz = sgx[(8 + g) * GXP + b]  + tb[HH + col];
            float xn = sgx[(16 + g) * GXP + b] + tb[2 * HH + col];
            float r = sigmoidf_(xr + ar[i] + bhr);
            float z = sigmoidf_(xz + az[i] + bhz);
            float n = tanhf(xn + r * (an[i] + bhn));
            hout[b * HH + col] = (1.0f - z) * n + z * hold[i];
            ar[i] = 0.0f; az[i] = 0.0f; an[i] = 0.0f;
        }

        flatbar(cta, tid, (unsigned)(t + 1));

        // ---- phase 2 (R9 verbatim): logits + masked argmax ----
        {
            const int b = cta;
            ((float4*)srow)[tid] = ((const float4*)&hout[b * HH])[tid];
            __syncthreads();
            for (int l = g; l < NL; l += 8) {
                float s = 0.0f;
                const float* wo = Wout + (size_t)l * HH;
#pragma unroll 8
                for (int k = mi; k < HH; k += 32) s += srow[k] * __ldg(&wo[k]);
#pragma unroll
                for (int off = 16; off > 0; off >>= 1)
                    s += __shfl_down_sync(0xffffffffu, s, off);
                if (mi == 0) slog[l] = s;
            }
            __syncthreads();
            if (tid == 0) {
                int pv = (int)(g_pt[b] & 31u);
                float best = -INFINITY;
                int bi = 0;
                float* orow = out + ((size_t)b * TT + t) * NL;
#pragma unroll
                for (int l = 0; l < NL; l++) {
                    float v = slog[l] + bout[l] + maskval(pv, l);
                    orow[l] = v;
                    if (v > best) { best = v; bi = l; }
                }
                g_pt[b] = ((unsigned)(t + 1) << 5) | (unsigned)bi;
            }
            __syncthreads();
        }
        cur ^= 1;
    }
}

// ---------------- launch ----------------
extern "C" void kernel_launch(void* const* d_in, const int* in_sizes, int n_in,
                              void* d_out, int out_size) {
    const float* we   = (const float*)d_in[0];
    const float* lemb = (const float*)d_in[1];
    const float* wih  = (const float*)d_in[2];
    const float* whh  = (const float*)d_in[3];
    const float* bih  = (const float*)d_in[4];
    const float* bhh  = (const float*)d_in[5];
    const float* wout = (const float*)d_in[6];
    const float* bout = (const float*)d_in[7];
    float* out = (float*)d_out;

    const int sh_gemm = (2 * 128 * APAD + 2 * 256 * APAD) * 4;            // 110,592 B
    const int sh_rec  = (24 * 1024 + 2 * BB * SHP + 24 * GXP + 1024) * 4; // 184,704 B
    cudaFuncSetAttribute(gxw_gemm_tc, cudaFuncAttributeMaxDynamicSharedMemorySize,
                         sh_gemm);
    cudaFuncSetAttribute(recurrent, cudaFuncAttributeMaxDynamicSharedMemorySize,
                         sh_rec);

    reset_state<<<512, 256>>>();
    build_table<<<dim3(G3 / 256, NL), 256>>>(lemb, wih, bih);
    presplit_A<<<4096, 256>>>(we);
    presplit_B<<<768, 256>>>(wih);
    gxw_gemm_tc<<<dim3(G3 / 256, (BB * TT) / 128), 256, sh_gemm>>>();
    recurrent<<<NCTA, 256, sh_rec>>>(whh, bhh, wout, bout, out);
}